// round 12
// baseline (speedup 1.0000x reference)
#include <cuda_runtime.h>

#define LBL 256
#define NBINS (LBL * LBL)          // 65536 bins
#define NWORDS (NBINS / 4)         // 16384 packed u32 words (u8 counters)
#define NQUADS (NWORDS / 4)        // 4096 uint4 per slice
#define GRID 148                   // one persistent CTA per SM (co-resident)
#define TPB 1024
#define NSLICE 160                 // padded (148 written, 12 always zero)
#define RGRID 128                  // tail-active blocks; each owns 2 rows
#define RWORDS (NWORDS / RGRID)    // 128 words = 32 uint4 quads
#define RQUADS (RWORDS / 4)        // 32
#define NSUB 32                    // slice-range splits
#define SPS (NSLICE / NSUB)        // 5 slices per sub (compile-time)

// Static device scratch. All counters re-zeroed by the epilogue block each
// run; g_rowsum/g_rowstat plainly overwritten; g_part slices 148..159 never
// written. => graph replays deterministic.
__device__ __align__(16) unsigned int g_C[NBINS];               // RED target
__device__ __align__(16) unsigned int g_part[NSLICE * NWORDS];  // 10.5 MB
__device__ unsigned int       g_rowsum[LBL];
__device__ unsigned long long g_rowstat[LBL];   // (maxv<<32)|maxcol over Cnz
__device__ unsigned long long g_col64[LBL];     // lo: colsum, hi: nz-cnt
__device__ unsigned int       g_pairs;
__device__ unsigned int       g_arrive;          // grid barrier counter
__device__ unsigned int       g_done;            // tail ticket

// ==========================================================================
// ONE persistent kernel: histogram -> grid barrier -> reduce+stats -> ticket
// -> epilogue. 148 blocks x 1024 threads, 64KB dynamic smem (hist buffer,
// reused as the reduce staging area after the barrier).
// ==========================================================================
__global__ void __launch_bounds__(TPB) fused_kernel(const int4* __restrict__ p4,
                                                    const int4* __restrict__ g4,
                                                    int n4,
                                                    float* __restrict__ out) {
    extern __shared__ unsigned int s_hist[];   // 64KB dynamic

    __shared__ uint4         s_val[RWORDS];
    __shared__ unsigned int  s_fl[RWORDS];
    __shared__ unsigned int       s_rowp[4];
    __shared__ unsigned long long s_maxp[4];
    __shared__ unsigned int       s_cntp[4];
    __shared__ unsigned int  s_pred_size[LBL];
    __shared__ unsigned int  s_gt_size[LBL];
    __shared__ unsigned int  s_inter[LBL];
    __shared__ short         s_best_p[LBL];
    __shared__ unsigned char s_used[LBL];
    __shared__ unsigned int  s_hasmask[LBL / 32];
    __shared__ unsigned int  s_cnt[4];   // ea, num_pred, num_gt, pairs
    __shared__ unsigned int  s_islast;

    const int tid = threadIdx.x;

    // ===================== Phase H: histogram (FROZEN) ====================
    // 50/50 per-pixel hybrid at the dual-pipe atomic ceiling:
    //   keys x,y -> byte-packed 64KB smem hist (per-SM ATOMS pipe)
    //   keys z,w -> global RED into g_C       (L2 atomic pipe)
#pragma unroll
    for (int i = tid; i < NWORDS; i += TPB) s_hist[i] = 0u;
    __syncthreads();

    {
        const int stride = GRID * TPB;
        int i = blockIdx.x * TPB + tid;

        for (; i + stride < n4; i += 2 * stride) {
            int4 pa = p4[i];
            int4 ga = g4[i];
            int4 pb = p4[i + stride];
            int4 gb = g4[i + stride];

            int a0 = (ga.x << 8) + pa.x;
            int a1 = (ga.y << 8) + pa.y;
            int a2 = (ga.z << 8) + pa.z;
            int a3 = (ga.w << 8) + pa.w;
            int b0 = (gb.x << 8) + pb.x;
            int b1 = (gb.y << 8) + pb.y;
            int b2 = (gb.z << 8) + pb.z;
            int b3 = (gb.w << 8) + pb.w;

            atomicAdd(&s_hist[a0 >> 2], 1u << ((a0 & 3) << 3));
            atomicAdd(&s_hist[a1 >> 2], 1u << ((a1 & 3) << 3));
            atomicAdd(&s_hist[b0 >> 2], 1u << ((b0 & 3) << 3));
            atomicAdd(&s_hist[b1 >> 2], 1u << ((b1 & 3) << 3));
            atomicAdd(&g_C[a2], 1u);
            atomicAdd(&g_C[a3], 1u);
            atomicAdd(&g_C[b2], 1u);
            atomicAdd(&g_C[b3], 1u);
        }
        if (i < n4) {
            int4 p = p4[i];
            int4 g = g4[i];
            int k0 = (g.x << 8) + p.x;
            int k1 = (g.y << 8) + p.y;
            int k2 = (g.z << 8) + p.z;
            int k3 = (g.w << 8) + p.w;
            atomicAdd(&s_hist[k0 >> 2], 1u << ((k0 & 3) << 3));
            atomicAdd(&s_hist[k1 >> 2], 1u << ((k1 & 3) << 3));
            atomicAdd(&g_C[k2], 1u);
            atomicAdd(&g_C[k3], 1u);
        }
    }
    __syncthreads();

    // Flush packed partial to this block's private slice.
    {
        uint4* dst = (uint4*)&g_part[(size_t)blockIdx.x * NWORDS];
        const uint4* src = (const uint4*)s_hist;
#pragma unroll
        for (int w = tid; w < NWORDS / 4; w += TPB) dst[w] = src[w];
    }

    // ===================== Grid-wide barrier ==============================
    // 148 blocks = 1/SM => all co-resident; spin is deadlock-free.
    __syncthreads();
    __threadfence();
    if (tid == 0) {
        atomicAdd(&g_arrive, 1u);
        while (*(volatile unsigned int*)&g_arrive < (unsigned)GRID) { }
    }
    __syncthreads();
    __threadfence();   // order subsequent g_part/g_C reads after the spin

    if (blockIdx.x >= RGRID) return;   // 20 blocks done; 128 run the tail

    // ===================== Phase R: reduce + matrix stats =================
    // Block b owns words [128b,128b+128) = rows 2b,2b+1 exclusively.
    uint4* s_acc = (uint4*)s_hist;     // reuse the dead 64KB hist buffer
    const int q   = tid & (RQUADS - 1);
    const int sub = tid >> 5;

    {   // 5 x LDG.128 per thread, packed-byte accumulate (__vadd4).
        const uint4* base = (const uint4*)g_part
                          + (size_t)(sub * SPS) * NQUADS
                          + blockIdx.x * RQUADS + q;
        uint4 acc = make_uint4(0u, 0u, 0u, 0u);
#pragma unroll
        for (int k = 0; k < SPS; k++) {
            uint4 w = __ldcs(base + (size_t)k * NQUADS);
            acc.x = __vadd4(acc.x, w.x);
            acc.y = __vadd4(acc.y, w.y);
            acc.z = __vadd4(acc.z, w.z);
            acc.w = __vadd4(acc.w, w.w);
        }
        s_acc[sub * RQUADS + q] = acc;
    }
    __syncthreads();

    if (tid < RWORDS) {   // finalize the block's 128 words
        const int w = blockIdx.x * RWORDS + tid;
        const int b = w << 2;
        const unsigned int* flat = (const unsigned int*)s_acc;
        unsigned int v0 = 0, v1 = 0, v2 = 0, v3 = 0;
#pragma unroll
        for (int s = 0; s < NSUB; s++) {
            unsigned int p = flat[s * RWORDS + tid];   // conflict-free
            v0 += p & 0xffu;
            v1 += (p >> 8) & 0xffu;
            v2 += (p >> 16) & 0xffu;
            v3 += (p >> 24);
        }
        uint4 r = *(const uint4*)&g_C[b];
        v0 += r.x; v1 += r.y; v2 += r.z; v3 += r.w;
        *(uint4*)&g_C[b] = make_uint4(0u, 0u, 0u, 0u);   // re-zero RED target

        const int row = w >> 6;
        const int c0  = (w & 63) << 2;
        const bool gnz = (row >= 1);

        unsigned int vv[4] = {v0, v1, v2, v3};
        unsigned long long pk = 0ull;
        unsigned int fl = 0;
#pragma unroll
        for (int j = 0; j < 4; j++) {
            bool valid = gnz && (c0 + j >= 1) && (vv[j] > 0u);
            if (valid) {
                fl |= 1u << j;
                unsigned long long p =
                    ((unsigned long long)vv[j] << 32) | (unsigned)(c0 + j);
                if (p > pk) pk = p;
            }
        }
        s_val[tid] = make_uint4(v0, v1, v2, v3);
        s_fl[tid]  = fl;

        unsigned int rtot = v0 + v1 + v2 + v3;
        unsigned long long pm = pk;
        unsigned int ctot = __popc(fl);
#pragma unroll
        for (int s = 16; s > 0; s >>= 1) {
            rtot += __shfl_xor_sync(0xffffffffu, rtot, s);
            unsigned long long o = __shfl_xor_sync(0xffffffffu, pm, s);
            if (o > pm) pm = o;
            ctot += __shfl_xor_sync(0xffffffffu, ctot, s);
        }
        const int wrp = tid >> 5;
        if ((tid & 31) == 0) {
            s_rowp[wrp] = rtot;
            s_maxp[wrp] = pm;
            s_cntp[wrp] = ctot;
        }
    }
    __syncthreads();

    // Column atomics: combine the block's two rows, 4 cols per thread.
    if (tid < 64) {
        uint4 lo = s_val[tid];
        uint4 hi = s_val[tid + 64];
        unsigned int fl_lo = s_fl[tid], fl_hi = s_fl[tid + 64];
        unsigned int vl[4] = {lo.x, lo.y, lo.z, lo.w};
        unsigned int vh[4] = {hi.x, hi.y, hi.z, hi.w};
        const int c0 = tid << 2;
#pragma unroll
        for (int j = 0; j < 4; j++) {
            unsigned int cs = vl[j] + vh[j];
            unsigned int cc = ((fl_lo >> j) & 1u) + ((fl_hi >> j) & 1u);
            unsigned long long add =
                (unsigned long long)cs + ((unsigned long long)cc << 32);
            if (add) atomicAdd(&g_col64[c0 + j], add);
        }
    }
    // Row stats: plain stores (exclusive ownership).
    if (tid == 0) {
        g_rowsum[2 * blockIdx.x]      = s_rowp[0] + s_rowp[1];
        g_rowsum[2 * blockIdx.x + 1]  = s_rowp[2] + s_rowp[3];
        unsigned long long m0 = s_maxp[0] > s_maxp[1] ? s_maxp[0] : s_maxp[1];
        unsigned long long m1 = s_maxp[2] > s_maxp[3] ? s_maxp[2] : s_maxp[3];
        g_rowstat[2 * blockIdx.x]     = m0;
        g_rowstat[2 * blockIdx.x + 1] = m1;
        unsigned int pc = s_cntp[0] + s_cntp[1] + s_cntp[2] + s_cntp[3];
        if (pc) atomicAdd(&g_pairs, pc);
    }

    // ---- Ticket: last tail block runs the epilogue.
    __syncthreads();
    __threadfence();
    if (tid == 0) {
        unsigned int t = atomicAdd(&g_done, 1u);
        s_islast = (t == (unsigned)(RGRID - 1)) ? 1u : 0u;
    }
    __syncthreads();
    if (!s_islast) return;

    // ===================== Phase E: epilogue ==============================
    const int lane = tid & 31;
    const int wid  = tid >> 5;

    if (tid == 0) {
        g_done = 0u;
        g_arrive = 0u;
        s_cnt[3] = g_pairs;   // pairs
        g_pairs = 0u;
        s_cnt[0] = 0u; s_cnt[1] = 0u; s_cnt[2] = 0u;
    }
    __syncthreads();

    if (tid < LBL) {
        unsigned int rowsum = g_rowsum[tid];
        unsigned long long rmx = g_rowstat[tid];
        unsigned long long c64 = g_col64[tid];
        g_col64[tid] = 0ull;   // re-zero for next replay

        unsigned int psize  = (unsigned int)c64;
        unsigned int colcnt = (unsigned int)(c64 >> 32);
        unsigned int mv     = (unsigned int)(rmx >> 32);
        int          mc     = (int)(rmx & 0xffffffffu);

        s_gt_size[tid]   = rowsum;
        s_pred_size[tid] = psize;
        s_used[tid]      = 0;

        bool has = (tid >= 1) && (2ull * mv > (unsigned long long)rowsum);
        s_best_p[tid] = (short)(has ? mc : 0);
        s_inter[tid]  = has ? mv : 0u;

        unsigned int hb = __ballot_sync(0xffffffffu, has);
        if (lane == 0) s_hasmask[wid] = hb;

        if (tid >= 1) {
            if (colcnt > 1u) atomicAdd(&s_cnt[0], 1u);   // ea
            if (psize  > 0u) atomicAdd(&s_cnt[1], 1u);   // num_pred
            if (rowsum > 0u) atomicAdd(&s_cnt[2], 1u);   // num_gt
        }
    }
    __syncthreads();

    if (tid == 0) {
        unsigned int ea       = s_cnt[0];
        unsigned int num_pred = s_cnt[1];
        unsigned int num_gt   = s_cnt[2];
        unsigned int pairs    = s_cnt[3];

        unsigned int tp = 0;
        float seg_sum = 0.0f;
#pragma unroll
        for (int w = 0; w < LBL / 32; w++) {
            unsigned int m = s_hasmask[w];
            while (m) {
                int bb = __ffs(m) - 1;
                m &= m - 1u;
                int gl = w * 32 + bb;
                int pl = s_best_p[gl];
                if (!s_used[pl]) {
                    unsigned int uni = s_gt_size[gl] + s_pred_size[pl] - s_inter[gl];
                    if (uni < 1u) uni = 1u;
                    seg_sum += (float)s_inter[gl] / (float)uni;
                    s_used[pl] = 1;
                    tp++;
                }
            }
        }
        float ng  = fmaxf((float)num_gt, 1.0f);
        float seg = seg_sum / ng;
        int ns = (int)pairs    - (int)tp;
        int fn = (int)num_gt   - (int)tp;
        int fp = (int)num_pred - (int)tp;
        float det = 1.0f - (float)(fp + fn + ns + (int)ea) / ng;

        bool both_empty = (num_gt == 0u) && (num_pred == 0u);
        bool any_empty  = (num_gt == 0u) || (num_pred == 0u);
        if (both_empty)     { seg = 1.0f; det = 1.0f; }
        else if (any_empty) { seg = 0.0f; det = 0.0f; }

        out[0] = seg;
        out[1] = det;
    }
}

extern "C" void kernel_launch(void* const* d_in, const int* in_sizes, int n_in,
                              void* d_out, int out_size) {
    const int* pred = (const int*)d_in[0];
    const int* gt   = (const int*)d_in[1];
    int n  = in_sizes[0];
    int n4 = n >> 2;

    cudaFuncSetAttribute(fused_kernel,
                         cudaFuncAttributeMaxDynamicSharedMemorySize, 65536);

    fused_kernel<<<GRID, TPB, 65536>>>((const int4*)pred, (const int4*)gt, n4,
                                       (float*)d_out);
}

// round 13
// speedup vs baseline: 1.3221x; 1.3221x over previous
#include <cuda_runtime.h>

#define LBL 256
#define NBINS (LBL * LBL)          // 65536 bins
#define NWORDS (NBINS / 4)         // 16384 packed u32 words (u8 counters)
#define GRID 148                   // hist: 1 CTA per SM
#define TPB 1024
#define NSLICE 152                 // padded slice count (148 written, 4 always zero)
#define RGRID 128                  // tail blocks; each owns 128 words = 2 rows
#define RWORDS (NWORDS / RGRID)    // 128
#define NSUB 8                     // slice-range splits per word
#define SPS (NSLICE / NSUB)        // 19 slices per sub (compile-time)

// Static device scratch. g_C / g_col64 / g_pairs / g_done re-zeroed in the
// tail each run; g_rowsum/g_rowstat plainly overwritten; g_part slices
// 148..151 never written (stay zero). => graph replays deterministic.
__device__ __align__(16) unsigned int g_C[NBINS];               // RED target
__device__ __align__(16) unsigned int g_part[NSLICE * NWORDS];  // 10 MB
__device__ unsigned int       g_rowsum[LBL];    // full row sums (gt_size)
__device__ unsigned long long g_rowstat[LBL];   // (maxv<<32)|maxcol over Cnz
__device__ unsigned long long g_col64[LBL];     // lo: colsum, hi: nz-cnt
__device__ unsigned int       g_pairs;
__device__ unsigned int       g_done;

// --------------------------------------------------------------------------
// Histogram (FROZEN at the dual-pipe atomic ceiling, 66.8us):
// 50/50 per-pixel hybrid, unrolled x2, front-batched loads. Kept as its own
// kernel: round-12 fusion collapsed ptxas's 42-reg front-batched schedule.
// --------------------------------------------------------------------------
__global__ void __launch_bounds__(TPB) hist_kernel(const int4* __restrict__ p4,
                                                   const int4* __restrict__ g4,
                                                   int n4) {
    extern __shared__ unsigned int s_hist[];   // NWORDS u32 = 64KB
    const int tid = threadIdx.x;

#pragma unroll
    for (int i = tid; i < NWORDS; i += TPB) s_hist[i] = 0u;
    __syncthreads();

    const int stride = GRID * TPB;
    int i = blockIdx.x * TPB + tid;

    for (; i + stride < n4; i += 2 * stride) {
        int4 pa = p4[i];
        int4 ga = g4[i];
        int4 pb = p4[i + stride];
        int4 gb = g4[i + stride];

        int a0 = (ga.x << 8) + pa.x;
        int a1 = (ga.y << 8) + pa.y;
        int a2 = (ga.z << 8) + pa.z;
        int a3 = (ga.w << 8) + pa.w;
        int b0 = (gb.x << 8) + pb.x;
        int b1 = (gb.y << 8) + pb.y;
        int b2 = (gb.z << 8) + pb.z;
        int b3 = (gb.w << 8) + pb.w;

        atomicAdd(&s_hist[a0 >> 2], 1u << ((a0 & 3) << 3));
        atomicAdd(&s_hist[a1 >> 2], 1u << ((a1 & 3) << 3));
        atomicAdd(&s_hist[b0 >> 2], 1u << ((b0 & 3) << 3));
        atomicAdd(&s_hist[b1 >> 2], 1u << ((b1 & 3) << 3));
        atomicAdd(&g_C[a2], 1u);
        atomicAdd(&g_C[a3], 1u);
        atomicAdd(&g_C[b2], 1u);
        atomicAdd(&g_C[b3], 1u);
    }
    if (i < n4) {
        int4 p = p4[i];
        int4 g = g4[i];
        int k0 = (g.x << 8) + p.x;
        int k1 = (g.y << 8) + p.y;
        int k2 = (g.z << 8) + p.z;
        int k3 = (g.w << 8) + p.w;
        atomicAdd(&s_hist[k0 >> 2], 1u << ((k0 & 3) << 3));
        atomicAdd(&s_hist[k1 >> 2], 1u << ((k1 & 3) << 3));
        atomicAdd(&g_C[k2], 1u);
        atomicAdd(&g_C[k3], 1u);
    }
    __syncthreads();

    uint4* dst = (uint4*)&g_part[(size_t)blockIdx.x * NWORDS];
    const uint4* src = (const uint4*)s_hist;
#pragma unroll
    for (int w = tid; w < NWORDS / 4; w += TPB) dst[w] = src[w];
}

// --------------------------------------------------------------------------
// Fused tail, 128 blocks x 1024 threads (round-10 verified, 15.3us = LSU
// dispatch floor). Block b owns words [128b,128b+128) = rows 2b and 2b+1
// EXCLUSIVELY (row stats = plain stores, no atomics, no re-zero). Columns
// cross blocks -> g_col64 atomics, combined across the block's two rows.
// Phase 2 (last block via ticket): 256-entry stats + ballot greedy.
// --------------------------------------------------------------------------
__global__ void __launch_bounds__(1024) tail_kernel(float* __restrict__ out) {
    __shared__ uint4         s_acc[NSUB][RWORDS];    // 16KB partial sums
    __shared__ uint4         s_val[RWORDS];          // finalized per-word bins
    __shared__ unsigned int  s_fl[RWORDS];           // per-word valid flags
    __shared__ unsigned int       s_rowp[4];
    __shared__ unsigned long long s_maxp[4];
    __shared__ unsigned int       s_cntp[4];
    __shared__ unsigned int  s_pred_size[LBL];
    __shared__ unsigned int  s_gt_size[LBL];
    __shared__ unsigned int  s_inter[LBL];
    __shared__ short         s_best_p[LBL];
    __shared__ unsigned char s_used[LBL];
    __shared__ unsigned int  s_hasmask[LBL / 32];
    __shared__ unsigned int  s_cnt[4];   // ea, num_pred, num_gt, pairs
    __shared__ unsigned int  s_islast;

    const int tid  = threadIdx.x;
    const int wloc = tid & (RWORDS - 1);
    const int sub  = tid >> 7;               // 0..7
    const int word = blockIdx.x * RWORDS + wloc;

    // ---- Phase 1a: each thread sums SPS=19 slices, fully unrolled.
    {
        unsigned int a0 = 0, a1 = 0, a2 = 0, a3 = 0;
        const unsigned int* base = g_part + (size_t)(sub * SPS) * NWORDS + word;
#pragma unroll
        for (int k = 0; k < SPS; k++) {
            unsigned int w = __ldcs(base + (size_t)k * NWORDS);
            a0 += w & 0xffu;
            a1 += (w >> 8) & 0xffu;
            a2 += (w >> 16) & 0xffu;
            a3 += (w >> 24);
        }
        s_acc[sub][wloc] = make_uint4(a0, a1, a2, a3);
    }
    __syncthreads();

    // ---- Phase 1b: threads 0..127 finalize the block's 128 words.
    if (tid < RWORDS) {
        const int w = blockIdx.x * RWORDS + tid;
        const int b = w << 2;
        unsigned int v0 = 0, v1 = 0, v2 = 0, v3 = 0;
#pragma unroll
        for (int s = 0; s < NSUB; s++) {
            uint4 t = s_acc[s][tid];
            v0 += t.x; v1 += t.y; v2 += t.z; v3 += t.w;
        }
        uint4 r = *(const uint4*)&g_C[b];
        v0 += r.x; v1 += r.y; v2 += r.z; v3 += r.w;
        *(uint4*)&g_C[b] = make_uint4(0u, 0u, 0u, 0u);   // re-zero RED target

        const int row = w >> 6;                // 2b or 2b+1
        const int c0  = (w & 63) << 2;
        const bool gnz = (row >= 1);

        unsigned int vv[4] = {v0, v1, v2, v3};
        unsigned long long pk = 0ull;
        unsigned int fl = 0;
#pragma unroll
        for (int j = 0; j < 4; j++) {
            bool valid = gnz && (c0 + j >= 1) && (vv[j] > 0u);
            if (valid) {
                fl |= 1u << j;
                unsigned long long p =
                    ((unsigned long long)vv[j] << 32) | (unsigned)(c0 + j);
                if (p > pk) pk = p;
            }
        }
        s_val[tid] = make_uint4(v0, v1, v2, v3);
        s_fl[tid]  = fl;

        unsigned int rtot = v0 + v1 + v2 + v3;
        unsigned long long pm = pk;
        unsigned int ctot = __popc(fl);
#pragma unroll
        for (int s = 16; s > 0; s >>= 1) {
            rtot += __shfl_xor_sync(0xffffffffu, rtot, s);
            unsigned long long o = __shfl_xor_sync(0xffffffffu, pm, s);
            if (o > pm) pm = o;
            ctot += __shfl_xor_sync(0xffffffffu, ctot, s);
        }
        const int wrp = tid >> 5;              // 0..3
        if ((tid & 31) == 0) {
            s_rowp[wrp] = rtot;
            s_maxp[wrp] = pm;
            s_cntp[wrp] = ctot;
        }
    }
    __syncthreads();

    // ---- Column atomics: combine the block's two rows, 4 cols per thread.
    if (tid < 64) {
        uint4 lo = s_val[tid];
        uint4 hi = s_val[tid + 64];
        unsigned int fl_lo = s_fl[tid], fl_hi = s_fl[tid + 64];
        unsigned int vl[4] = {lo.x, lo.y, lo.z, lo.w};
        unsigned int vh[4] = {hi.x, hi.y, hi.z, hi.w};
        const int c0 = tid << 2;
#pragma unroll
        for (int j = 0; j < 4; j++) {
            unsigned int cs  = vl[j] + vh[j];
            unsigned int cc  = ((fl_lo >> j) & 1u) + ((fl_hi >> j) & 1u);
            unsigned long long add =
                (unsigned long long)cs + ((unsigned long long)cc << 32);
            if (add) atomicAdd(&g_col64[c0 + j], add);
        }
    }
    // ---- Row stats: plain stores (exclusive ownership).
    if (tid == 0) {
        g_rowsum[2 * blockIdx.x]      = s_rowp[0] + s_rowp[1];
        g_rowsum[2 * blockIdx.x + 1]  = s_rowp[2] + s_rowp[3];
        unsigned long long m0 = s_maxp[0] > s_maxp[1] ? s_maxp[0] : s_maxp[1];
        unsigned long long m1 = s_maxp[2] > s_maxp[3] ? s_maxp[2] : s_maxp[3];
        g_rowstat[2 * blockIdx.x]     = m0;
        g_rowstat[2 * blockIdx.x + 1] = m1;
        unsigned int pc = s_cntp[0] + s_cntp[1] + s_cntp[2] + s_cntp[3];
        if (pc) atomicAdd(&g_pairs, pc);
    }

    // ---- Ticket: last block to finish runs the epilogue.
    __syncthreads();
    __threadfence();
    if (tid == 0) {
        unsigned int t = atomicAdd(&g_done, 1u);
        s_islast = (t == (unsigned)(gridDim.x - 1)) ? 1u : 0u;
    }
    __syncthreads();
    if (!s_islast) return;

    // ---- Phase 2: epilogue on the 256-entry stat arrays.
    const int lane = tid & 31;
    const int wid  = tid >> 5;

    if (tid == 0) {
        g_done = 0u;
        s_cnt[3] = g_pairs;   // pairs
        g_pairs = 0u;
        s_cnt[0] = 0u; s_cnt[1] = 0u; s_cnt[2] = 0u;
    }
    __syncthreads();

    if (tid < LBL) {
        unsigned int rowsum = g_rowsum[tid];
        unsigned long long rmx = g_rowstat[tid];
        unsigned long long c64 = g_col64[tid];
        g_col64[tid] = 0ull;   // re-zero for next replay

        unsigned int psize  = (unsigned int)c64;
        unsigned int colcnt = (unsigned int)(c64 >> 32);
        unsigned int mv     = (unsigned int)(rmx >> 32);
        int          mc     = (int)(rmx & 0xffffffffu);

        s_gt_size[tid]   = rowsum;
        s_pred_size[tid] = psize;
        s_used[tid]      = 0;

        bool has = (tid >= 1) && (2ull * mv > (unsigned long long)rowsum);
        s_best_p[tid] = (short)(has ? mc : 0);
        s_inter[tid]  = has ? mv : 0u;

        unsigned int hb = __ballot_sync(0xffffffffu, has);
        if (lane == 0) s_hasmask[wid] = hb;

        if (tid >= 1) {
            if (colcnt > 1u) atomicAdd(&s_cnt[0], 1u);   // ea
            if (psize  > 0u) atomicAdd(&s_cnt[1], 1u);   // num_pred
            if (rowsum > 0u) atomicAdd(&s_cnt[2], 1u);   // num_gt
        }
    }
    __syncthreads();

    if (tid == 0) {
        unsigned int ea       = s_cnt[0];
        unsigned int num_pred = s_cnt[1];
        unsigned int num_gt   = s_cnt[2];
        unsigned int pairs    = s_cnt[3];

        unsigned int tp = 0;
        float seg_sum = 0.0f;
#pragma unroll
        for (int w = 0; w < LBL / 32; w++) {
            unsigned int m = s_hasmask[w];
            while (m) {
                int bb = __ffs(m) - 1;
                m &= m - 1u;
                int gl = w * 32 + bb;
                int pl = s_best_p[gl];
                if (!s_used[pl]) {
                    unsigned int uni = s_gt_size[gl] + s_pred_size[pl] - s_inter[gl];
                    if (uni < 1u) uni = 1u;
                    seg_sum += (float)s_inter[gl] / (float)uni;
                    s_used[pl] = 1;
                    tp++;
                }
            }
        }
        float ng  = fmaxf((float)num_gt, 1.0f);
        float seg = seg_sum / ng;
        int ns = (int)pairs    - (int)tp;
        int fn = (int)num_gt   - (int)tp;
        int fp = (int)num_pred - (int)tp;
        float det = 1.0f - (float)(fp + fn + ns + (int)ea) / ng;

        bool both_empty = (num_gt == 0u) && (num_pred == 0u);
        bool any_empty  = (num_gt == 0u) || (num_pred == 0u);
        if (both_empty)     { seg = 1.0f; det = 1.0f; }
        else if (any_empty) { seg = 0.0f; det = 0.0f; }

        out[0] = seg;
        out[1] = det;
    }
}

extern "C" void kernel_launch(void* const* d_in, const int* in_sizes, int n_in,
                              void* d_out, int out_size) {
    const int* pred = (const int*)d_in[0];
    const int* gt   = (const int*)d_in[1];
    int n  = in_sizes[0];
    int n4 = n >> 2;

    cudaFuncSetAttribute(hist_kernel,
                         cudaFuncAttributeMaxDynamicSharedMemorySize, 65536);

    hist_kernel<<<GRID, TPB, 65536>>>((const int4*)pred, (const int4*)gt, n4);
    tail_kernel<<<RGRID, 1024>>>((float*)d_out);
}

// round 14
// speedup vs baseline: 1.3329x; 1.0082x over previous
#include <cuda_runtime.h>
#include <cooperative_groups.h>

namespace cg = cooperative_groups;

#define LBL 256
#define NBINS (LBL * LBL)          // 65536 bins
#define NWORDS (NBINS / 4)         // 16384 packed u32 words (u8 counters)
#define GRID 148                   // hist: 1 CTA per SM, 74 clusters of 2
#define TPB 1024
#define NCLUST (GRID / 2)          // 74 combined slices
#define NSLICE 80                  // padded (74 written, 6 always zero)
#define RGRID 128                  // tail blocks; each owns 128 words = 2 rows
#define RWORDS (NWORDS / RGRID)    // 128
#define NSUB 8                     // slice-range splits per word
#define SPS (NSLICE / NSUB)        // 10 slices per sub (compile-time)
#define HALF4 (NWORDS / 4 / 2)     // 2048 uint4 per half-histogram

// Static device scratch. g_C / g_col64 / g_pairs / g_done re-zeroed in the
// tail each run; g_rowsum/g_rowstat plainly overwritten; g_part slices
// 74..79 never written (stay zero). => graph replays deterministic.
__device__ __align__(16) unsigned int g_C[NBINS];               // RED target
__device__ __align__(16) unsigned int g_part[NSLICE * NWORDS];  // 5.2 MB
__device__ unsigned int       g_rowsum[LBL];    // full row sums (gt_size)
__device__ unsigned long long g_rowstat[LBL];   // (maxv<<32)|maxcol over Cnz
__device__ unsigned long long g_col64[LBL];     // lo: colsum, hi: nz-cnt
__device__ unsigned int       g_pairs;
__device__ unsigned int       g_done;

// --------------------------------------------------------------------------
// Histogram: 50/50 per-pixel hybrid mainloop (FROZEN, byte-identical to the
// verified 66.8us version). NEW: cluster-of-2 DSMEM combine at flush time —
// each CTA merges its half of the histogram with its peer's half (__vadd4)
// and flushes 32KB, halving the partials the tail must read (9.7 -> 4.9MB).
// --------------------------------------------------------------------------
__global__ void __launch_bounds__(TPB) __cluster_dims__(2, 1, 1)
hist_kernel(const int4* __restrict__ p4,
            const int4* __restrict__ g4,
            int n4) {
    extern __shared__ unsigned int s_hist[];   // NWORDS u32 = 64KB
    const int tid = threadIdx.x;

#pragma unroll
    for (int i = tid; i < NWORDS; i += TPB) s_hist[i] = 0u;
    __syncthreads();

    const int stride = GRID * TPB;
    int i = blockIdx.x * TPB + tid;

    for (; i + stride < n4; i += 2 * stride) {
        int4 pa = p4[i];
        int4 ga = g4[i];
        int4 pb = p4[i + stride];
        int4 gb = g4[i + stride];

        int a0 = (ga.x << 8) + pa.x;
        int a1 = (ga.y << 8) + pa.y;
        int a2 = (ga.z << 8) + pa.z;
        int a3 = (ga.w << 8) + pa.w;
        int b0 = (gb.x << 8) + pb.x;
        int b1 = (gb.y << 8) + pb.y;
        int b2 = (gb.z << 8) + pb.z;
        int b3 = (gb.w << 8) + pb.w;

        atomicAdd(&s_hist[a0 >> 2], 1u << ((a0 & 3) << 3));
        atomicAdd(&s_hist[a1 >> 2], 1u << ((a1 & 3) << 3));
        atomicAdd(&s_hist[b0 >> 2], 1u << ((b0 & 3) << 3));
        atomicAdd(&s_hist[b1 >> 2], 1u << ((b1 & 3) << 3));
        atomicAdd(&g_C[a2], 1u);
        atomicAdd(&g_C[a3], 1u);
        atomicAdd(&g_C[b2], 1u);
        atomicAdd(&g_C[b3], 1u);
    }
    if (i < n4) {
        int4 p = p4[i];
        int4 g = g4[i];
        int k0 = (g.x << 8) + p.x;
        int k1 = (g.y << 8) + p.y;
        int k2 = (g.z << 8) + p.z;
        int k3 = (g.w << 8) + p.w;
        atomicAdd(&s_hist[k0 >> 2], 1u << ((k0 & 3) << 3));
        atomicAdd(&s_hist[k1 >> 2], 1u << ((k1 & 3) << 3));
        atomicAdd(&g_C[k2], 1u);
        atomicAdd(&g_C[k3], 1u);
    }
    __syncthreads();

    // ---- Cluster combine + flush. Rank r owns combined words
    //      [r*HALF4, (r+1)*HALF4) (uint4 units); peer half read via DSMEM.
    cg::cluster_group cluster = cg::this_cluster();
    cluster.sync();   // peer's counting complete before we read its smem

    {
        const unsigned int rank = cluster.block_rank();
        const int clid = blockIdx.x >> 1;
        const uint4* own  = (const uint4*)s_hist;
        const uint4* peer = (const uint4*)cluster.map_shared_rank(
                                (void*)s_hist, rank ^ 1u);
        uint4* dst = (uint4*)&g_part[(size_t)clid * NWORDS];
        const int base = rank * HALF4;
#pragma unroll
        for (int t = tid; t < HALF4; t += TPB) {
            uint4 a = own[base + t];
            uint4 b = peer[base + t];
            a.x = __vadd4(a.x, b.x);
            a.y = __vadd4(a.y, b.y);
            a.z = __vadd4(a.z, b.z);
            a.w = __vadd4(a.w, b.w);
            dst[base + t] = a;
        }
    }
    cluster.sync();   // peer done reading my smem before I exit
}

// --------------------------------------------------------------------------
// Fused tail, 128 blocks x 1024 threads (round-10 structure, now over 74
// combined slices). Block b owns words [128b,128b+128) = rows 2b and 2b+1
// EXCLUSIVELY (row stats = plain stores, no atomics). Columns cross blocks
// -> g_col64 atomics, combined across the block's two rows.
// Phase 2 (last block via ticket): 256-entry stats + ballot greedy.
// --------------------------------------------------------------------------
__global__ void __launch_bounds__(1024) tail_kernel(float* __restrict__ out) {
    __shared__ uint4         s_acc[NSUB][RWORDS];    // 16KB partial sums
    __shared__ uint4         s_val[RWORDS];          // finalized per-word bins
    __shared__ unsigned int  s_fl[RWORDS];           // per-word valid flags
    __shared__ unsigned int       s_rowp[4];
    __shared__ unsigned long long s_maxp[4];
    __shared__ unsigned int       s_cntp[4];
    __shared__ unsigned int  s_pred_size[LBL];
    __shared__ unsigned int  s_gt_size[LBL];
    __shared__ unsigned int  s_inter[LBL];
    __shared__ short         s_best_p[LBL];
    __shared__ unsigned char s_used[LBL];
    __shared__ unsigned int  s_hasmask[LBL / 32];
    __shared__ unsigned int  s_cnt[4];   // ea, num_pred, num_gt, pairs
    __shared__ unsigned int  s_islast;

    const int tid  = threadIdx.x;
    const int wloc = tid & (RWORDS - 1);
    const int sub  = tid >> 7;               // 0..7
    const int word = blockIdx.x * RWORDS + wloc;

    // ---- Phase 1a: each thread sums SPS=10 slices, fully unrolled.
    {
        unsigned int a0 = 0, a1 = 0, a2 = 0, a3 = 0;
        const unsigned int* base = g_part + (size_t)(sub * SPS) * NWORDS + word;
#pragma unroll
        for (int k = 0; k < SPS; k++) {
            unsigned int w = __ldcs(base + (size_t)k * NWORDS);
            a0 += w & 0xffu;
            a1 += (w >> 8) & 0xffu;
            a2 += (w >> 16) & 0xffu;
            a3 += (w >> 24);
        }
        s_acc[sub][wloc] = make_uint4(a0, a1, a2, a3);
    }
    __syncthreads();

    // ---- Phase 1b: threads 0..127 finalize the block's 128 words.
    if (tid < RWORDS) {
        const int w = blockIdx.x * RWORDS + tid;
        const int b = w << 2;
        unsigned int v0 = 0, v1 = 0, v2 = 0, v3 = 0;
#pragma unroll
        for (int s = 0; s < NSUB; s++) {
            uint4 t = s_acc[s][tid];
            v0 += t.x; v1 += t.y; v2 += t.z; v3 += t.w;
        }
        uint4 r = *(const uint4*)&g_C[b];
        v0 += r.x; v1 += r.y; v2 += r.z; v3 += r.w;
        *(uint4*)&g_C[b] = make_uint4(0u, 0u, 0u, 0u);   // re-zero RED target

        const int row = w >> 6;                // 2b or 2b+1
        const int c0  = (w & 63) << 2;
        const bool gnz = (row >= 1);

        unsigned int vv[4] = {v0, v1, v2, v3};
        unsigned long long pk = 0ull;
        unsigned int fl = 0;
#pragma unroll
        for (int j = 0; j < 4; j++) {
            bool valid = gnz && (c0 + j >= 1) && (vv[j] > 0u);
            if (valid) {
                fl |= 1u << j;
                unsigned long long p =
                    ((unsigned long long)vv[j] << 32) | (unsigned)(c0 + j);
                if (p > pk) pk = p;
            }
        }
        s_val[tid] = make_uint4(v0, v1, v2, v3);
        s_fl[tid]  = fl;

        unsigned int rtot = v0 + v1 + v2 + v3;
        unsigned long long pm = pk;
        unsigned int ctot = __popc(fl);
#pragma unroll
        for (int s = 16; s > 0; s >>= 1) {
            rtot += __shfl_xor_sync(0xffffffffu, rtot, s);
            unsigned long long o = __shfl_xor_sync(0xffffffffu, pm, s);
            if (o > pm) pm = o;
            ctot += __shfl_xor_sync(0xffffffffu, ctot, s);
        }
        const int wrp = tid >> 5;              // 0..3
        if ((tid & 31) == 0) {
            s_rowp[wrp] = rtot;
            s_maxp[wrp] = pm;
            s_cntp[wrp] = ctot;
        }
    }
    __syncthreads();

    // ---- Column atomics: combine the block's two rows, 4 cols per thread.
    if (tid < 64) {
        uint4 lo = s_val[tid];
        uint4 hi = s_val[tid + 64];
        unsigned int fl_lo = s_fl[tid], fl_hi = s_fl[tid + 64];
        unsigned int vl[4] = {lo.x, lo.y, lo.z, lo.w};
        unsigned int vh[4] = {hi.x, hi.y, hi.z, hi.w};
        const int c0 = tid << 2;
#pragma unroll
        for (int j = 0; j < 4; j++) {
            unsigned int cs  = vl[j] + vh[j];
            unsigned int cc  = ((fl_lo >> j) & 1u) + ((fl_hi >> j) & 1u);
            unsigned long long add =
                (unsigned long long)cs + ((unsigned long long)cc << 32);
            if (add) atomicAdd(&g_col64[c0 + j], add);
        }
    }
    // ---- Row stats: plain stores (exclusive ownership).
    if (tid == 0) {
        g_rowsum[2 * blockIdx.x]      = s_rowp[0] + s_rowp[1];
        g_rowsum[2 * blockIdx.x + 1]  = s_rowp[2] + s_rowp[3];
        unsigned long long m0 = s_maxp[0] > s_maxp[1] ? s_maxp[0] : s_maxp[1];
        unsigned long long m1 = s_maxp[2] > s_maxp[3] ? s_maxp[2] : s_maxp[3];
        g_rowstat[2 * blockIdx.x]     = m0;
        g_rowstat[2 * blockIdx.x + 1] = m1;
        unsigned int pc = s_cntp[0] + s_cntp[1] + s_cntp[2] + s_cntp[3];
        if (pc) atomicAdd(&g_pairs, pc);
    }

    // ---- Ticket: last block to finish runs the epilogue.
    __syncthreads();
    __threadfence();
    if (tid == 0) {
        unsigned int t = atomicAdd(&g_done, 1u);
        s_islast = (t == (unsigned)(gridDim.x - 1)) ? 1u : 0u;
    }
    __syncthreads();
    if (!s_islast) return;

    // ---- Phase 2: epilogue on the 256-entry stat arrays.
    const int lane = tid & 31;
    const int wid  = tid >> 5;

    if (tid == 0) {
        g_done = 0u;
        s_cnt[3] = g_pairs;   // pairs
        g_pairs = 0u;
        s_cnt[0] = 0u; s_cnt[1] = 0u; s_cnt[2] = 0u;
    }
    __syncthreads();

    if (tid < LBL) {
        unsigned int rowsum = g_rowsum[tid];
        unsigned long long rmx = g_rowstat[tid];
        unsigned long long c64 = g_col64[tid];
        g_col64[tid] = 0ull;   // re-zero for next replay

        unsigned int psize  = (unsigned int)c64;
        unsigned int colcnt = (unsigned int)(c64 >> 32);
        unsigned int mv     = (unsigned int)(rmx >> 32);
        int          mc     = (int)(rmx & 0xffffffffu);

        s_gt_size[tid]   = rowsum;
        s_pred_size[tid] = psize;
        s_used[tid]      = 0;

        bool has = (tid >= 1) && (2ull * mv > (unsigned long long)rowsum);
        s_best_p[tid] = (short)(has ? mc : 0);
        s_inter[tid]  = has ? mv : 0u;

        unsigned int hb = __ballot_sync(0xffffffffu, has);
        if (lane == 0) s_hasmask[wid] = hb;

        if (tid >= 1) {
            if (colcnt > 1u) atomicAdd(&s_cnt[0], 1u);   // ea
            if (psize  > 0u) atomicAdd(&s_cnt[1], 1u);   // num_pred
            if (rowsum > 0u) atomicAdd(&s_cnt[2], 1u);   // num_gt
        }
    }
    __syncthreads();

    if (tid == 0) {
        unsigned int ea       = s_cnt[0];
        unsigned int num_pred = s_cnt[1];
        unsigned int num_gt   = s_cnt[2];
        unsigned int pairs    = s_cnt[3];

        unsigned int tp = 0;
        float seg_sum = 0.0f;
#pragma unroll
        for (int w = 0; w < LBL / 32; w++) {
            unsigned int m = s_hasmask[w];
            while (m) {
                int bb = __ffs(m) - 1;
                m &= m - 1u;
                int gl = w * 32 + bb;
                int pl = s_best_p[gl];
                if (!s_used[pl]) {
                    unsigned int uni = s_gt_size[gl] + s_pred_size[pl] - s_inter[gl];
                    if (uni < 1u) uni = 1u;
                    seg_sum += (float)s_inter[gl] / (float)uni;
                    s_used[pl] = 1;
                    tp++;
                }
            }
        }
        float ng  = fmaxf((float)num_gt, 1.0f);
        float seg = seg_sum / ng;
        int ns = (int)pairs    - (int)tp;
        int fn = (int)num_gt   - (int)tp;
        int fp = (int)num_pred - (int)tp;
        float det = 1.0f - (float)(fp + fn + ns + (int)ea) / ng;

        bool both_empty = (num_gt == 0u) && (num_pred == 0u);
        bool any_empty  = (num_gt == 0u) || (num_pred == 0u);
        if (both_empty)     { seg = 1.0f; det = 1.0f; }
        else if (any_empty) { seg = 0.0f; det = 0.0f; }

        out[0] = seg;
        out[1] = det;
    }
}

extern "C" void kernel_launch(void* const* d_in, const int* in_sizes, int n_in,
                              void* d_out, int out_size) {
    const int* pred = (const int*)d_in[0];
    const int* gt   = (const int*)d_in[1];
    int n  = in_sizes[0];
    int n4 = n >> 2;

    cudaFuncSetAttribute(hist_kernel,
                         cudaFuncAttributeMaxDynamicSharedMemorySize, 65536);

    hist_kernel<<<GRID, TPB, 65536>>>((const int4*)pred, (const int4*)gt, n4);
    tail_kernel<<<RGRID, 1024>>>((float*)d_out);
}

// round 15
// speedup vs baseline: 1.3595x; 1.0199x over previous
#include <cuda_runtime.h>
#include <cooperative_groups.h>

namespace cg = cooperative_groups;

#define LBL 256
#define NBINS (LBL * LBL)          // 65536 bins
#define NWORDS (NBINS / 4)         // 16384 packed u32 words (u8 counters)
#define GRID 148                   // hist: 1 CTA per SM, 74 clusters of 2
#define TPB 1024
#define NCLUST (GRID / 2)          // 74 combined slices
#define NSLICE 80                  // padded (74 written, 6 always zero)
#define RGRID 128                  // tail blocks; each owns 128 words = 2 rows
#define RWORDS (NWORDS / RGRID)    // 128
#define NSUB 8                     // slice-range splits per word
#define SPS (NSLICE / NSUB)        // 10 slices per sub (compile-time)
#define HALF4 (NWORDS / 4 / 2)     // 2048 uint4 per half-histogram

// Static device scratch. g_C / g_col64 / g_pairs / g_done re-zeroed in the
// tail each run; g_rowsum/g_rowstat plainly overwritten; g_part slices
// 74..79 never written (stay zero). => graph replays deterministic.
__device__ __align__(16) unsigned int g_C[NBINS];               // RED target
__device__ __align__(16) unsigned int g_part[NSLICE * NWORDS];  // 5.2 MB
__device__ unsigned int       g_rowsum[LBL];    // full row sums (gt_size)
__device__ unsigned long long g_rowstat[LBL];   // (maxv<<32)|maxcol over Cnz
__device__ unsigned long long g_col64[LBL];     // lo: colsum, hi: nz-cnt
__device__ unsigned int       g_pairs;
__device__ unsigned int       g_done;

// --------------------------------------------------------------------------
// Histogram: 50/50 per-pixel hybrid mainloop (FROZEN at the dual-pipe
// atomic ceiling) + cluster-of-2 DSMEM combine at flush (74 x 64KB slices).
// NEW: PDL trigger after the mainloop so the tail grid launches while the
// combine + flush drains.
// --------------------------------------------------------------------------
__global__ void __launch_bounds__(TPB) __cluster_dims__(2, 1, 1)
hist_kernel(const int4* __restrict__ p4,
            const int4* __restrict__ g4,
            int n4) {
    extern __shared__ unsigned int s_hist[];   // NWORDS u32 = 64KB
    const int tid = threadIdx.x;

#pragma unroll
    for (int i = tid; i < NWORDS; i += TPB) s_hist[i] = 0u;
    __syncthreads();

    const int stride = GRID * TPB;
    int i = blockIdx.x * TPB + tid;

    for (; i + stride < n4; i += 2 * stride) {
        int4 pa = p4[i];
        int4 ga = g4[i];
        int4 pb = p4[i + stride];
        int4 gb = g4[i + stride];

        int a0 = (ga.x << 8) + pa.x;
        int a1 = (ga.y << 8) + pa.y;
        int a2 = (ga.z << 8) + pa.z;
        int a3 = (ga.w << 8) + pa.w;
        int b0 = (gb.x << 8) + pb.x;
        int b1 = (gb.y << 8) + pb.y;
        int b2 = (gb.z << 8) + pb.z;
        int b3 = (gb.w << 8) + pb.w;

        atomicAdd(&s_hist[a0 >> 2], 1u << ((a0 & 3) << 3));
        atomicAdd(&s_hist[a1 >> 2], 1u << ((a1 & 3) << 3));
        atomicAdd(&s_hist[b0 >> 2], 1u << ((b0 & 3) << 3));
        atomicAdd(&s_hist[b1 >> 2], 1u << ((b1 & 3) << 3));
        atomicAdd(&g_C[a2], 1u);
        atomicAdd(&g_C[a3], 1u);
        atomicAdd(&g_C[b2], 1u);
        atomicAdd(&g_C[b3], 1u);
    }
    if (i < n4) {
        int4 p = p4[i];
        int4 g = g4[i];
        int k0 = (g.x << 8) + p.x;
        int k1 = (g.y << 8) + p.y;
        int k2 = (g.z << 8) + p.z;
        int k3 = (g.w << 8) + p.w;
        atomicAdd(&s_hist[k0 >> 2], 1u << ((k0 & 3) << 3));
        atomicAdd(&s_hist[k1 >> 2], 1u << ((k1 & 3) << 3));
        atomicAdd(&g_C[k2], 1u);
        atomicAdd(&g_C[k3], 1u);
    }
    __syncthreads();

    // PDL: mainloop done — let the dependent tail grid start dispatching
    // while we combine + flush. Tail waits on full completion via
    // cudaGridDependencySynchronize() before reading our output.
    cudaTriggerProgrammaticLaunchCompletion();

    // ---- Cluster combine + flush. Rank r owns combined words
    //      [r*HALF4, (r+1)*HALF4) (uint4 units); peer half read via DSMEM.
    cg::cluster_group cluster = cg::this_cluster();
    cluster.sync();   // peer's counting complete before we read its smem

    {
        const unsigned int rank = cluster.block_rank();
        const int clid = blockIdx.x >> 1;
        const uint4* own  = (const uint4*)s_hist;
        const uint4* peer = (const uint4*)cluster.map_shared_rank(
                                (void*)s_hist, rank ^ 1u);
        uint4* dst = (uint4*)&g_part[(size_t)clid * NWORDS];
        const int base = rank * HALF4;
#pragma unroll
        for (int t = tid; t < HALF4; t += TPB) {
            uint4 a = own[base + t];
            uint4 b = peer[base + t];
            a.x = __vadd4(a.x, b.x);
            a.y = __vadd4(a.y, b.y);
            a.z = __vadd4(a.z, b.z);
            a.w = __vadd4(a.w, b.w);
            dst[base + t] = a;
        }
    }
    cluster.sync();   // peer done reading my smem before I exit
}

// --------------------------------------------------------------------------
// Fused tail, 128 blocks x 1024 threads, launched with PDL so its ramp
// overlaps hist's flush. Block b owns words [128b,128b+128) = rows 2b,2b+1
// EXCLUSIVELY (row stats = plain stores). Columns cross blocks -> g_col64
// atomics. Phase 2 (last block via ticket): 256-entry stats + greedy.
// --------------------------------------------------------------------------
__global__ void __launch_bounds__(1024) tail_kernel(float* __restrict__ out) {
    __shared__ uint4         s_acc[NSUB][RWORDS];    // 16KB partial sums
    __shared__ uint4         s_val[RWORDS];          // finalized per-word bins
    __shared__ unsigned int  s_fl[RWORDS];           // per-word valid flags
    __shared__ unsigned int       s_rowp[4];
    __shared__ unsigned long long s_maxp[4];
    __shared__ unsigned int       s_cntp[4];
    __shared__ unsigned int  s_pred_size[LBL];
    __shared__ unsigned int  s_gt_size[LBL];
    __shared__ unsigned int  s_inter[LBL];
    __shared__ short         s_best_p[LBL];
    __shared__ unsigned char s_used[LBL];
    __shared__ unsigned int  s_hasmask[LBL / 32];
    __shared__ unsigned int  s_cnt[4];   // ea, num_pred, num_gt, pairs
    __shared__ unsigned int  s_islast;

    const int tid  = threadIdx.x;
    const int wloc = tid & (RWORDS - 1);
    const int sub  = tid >> 7;               // 0..7
    const int word = blockIdx.x * RWORDS + wloc;
    const unsigned int* base = g_part + (size_t)(sub * SPS) * NWORDS + word;

    // Wait for the hist grid to fully complete before reading g_part / g_C.
    cudaGridDependencySynchronize();

    // ---- Phase 1a: each thread sums SPS=10 slices, fully unrolled.
    {
        unsigned int a0 = 0, a1 = 0, a2 = 0, a3 = 0;
#pragma unroll
        for (int k = 0; k < SPS; k++) {
            unsigned int w = __ldcs(base + (size_t)k * NWORDS);
            a0 += w & 0xffu;
            a1 += (w >> 8) & 0xffu;
            a2 += (w >> 16) & 0xffu;
            a3 += (w >> 24);
        }
        s_acc[sub][wloc] = make_uint4(a0, a1, a2, a3);
    }
    __syncthreads();

    // ---- Phase 1b: threads 0..127 finalize the block's 128 words.
    if (tid < RWORDS) {
        const int w = blockIdx.x * RWORDS + tid;
        const int b = w << 2;
        unsigned int v0 = 0, v1 = 0, v2 = 0, v3 = 0;
#pragma unroll
        for (int s = 0; s < NSUB; s++) {
            uint4 t = s_acc[s][tid];
            v0 += t.x; v1 += t.y; v2 += t.z; v3 += t.w;
        }
        uint4 r = *(const uint4*)&g_C[b];
        v0 += r.x; v1 += r.y; v2 += r.z; v3 += r.w;
        *(uint4*)&g_C[b] = make_uint4(0u, 0u, 0u, 0u);   // re-zero RED target

        const int row = w >> 6;                // 2b or 2b+1
        const int c0  = (w & 63) << 2;
        const bool gnz = (row >= 1);

        unsigned int vv[4] = {v0, v1, v2, v3};
        unsigned long long pk = 0ull;
        unsigned int fl = 0;
#pragma unroll
        for (int j = 0; j < 4; j++) {
            bool valid = gnz && (c0 + j >= 1) && (vv[j] > 0u);
            if (valid) {
                fl |= 1u << j;
                unsigned long long p =
                    ((unsigned long long)vv[j] << 32) | (unsigned)(c0 + j);
                if (p > pk) pk = p;
            }
        }
        s_val[tid] = make_uint4(v0, v1, v2, v3);
        s_fl[tid]  = fl;

        unsigned int rtot = v0 + v1 + v2 + v3;
        unsigned long long pm = pk;
        unsigned int ctot = __popc(fl);
#pragma unroll
        for (int s = 16; s > 0; s >>= 1) {
            rtot += __shfl_xor_sync(0xffffffffu, rtot, s);
            unsigned long long o = __shfl_xor_sync(0xffffffffu, pm, s);
            if (o > pm) pm = o;
            ctot += __shfl_xor_sync(0xffffffffu, ctot, s);
        }
        const int wrp = tid >> 5;              // 0..3
        if ((tid & 31) == 0) {
            s_rowp[wrp] = rtot;
            s_maxp[wrp] = pm;
            s_cntp[wrp] = ctot;
        }
    }
    __syncthreads();

    // ---- Column atomics: combine the block's two rows, 4 cols per thread.
    if (tid < 64) {
        uint4 lo = s_val[tid];
        uint4 hi = s_val[tid + 64];
        unsigned int fl_lo = s_fl[tid], fl_hi = s_fl[tid + 64];
        unsigned int vl[4] = {lo.x, lo.y, lo.z, lo.w};
        unsigned int vh[4] = {hi.x, hi.y, hi.z, hi.w};
        const int c0 = tid << 2;
#pragma unroll
        for (int j = 0; j < 4; j++) {
            unsigned int cs  = vl[j] + vh[j];
            unsigned int cc  = ((fl_lo >> j) & 1u) + ((fl_hi >> j) & 1u);
            unsigned long long add =
                (unsigned long long)cs + ((unsigned long long)cc << 32);
            if (add) atomicAdd(&g_col64[c0 + j], add);
        }
    }
    // ---- Row stats: plain stores (exclusive ownership).
    if (tid == 0) {
        g_rowsum[2 * blockIdx.x]      = s_rowp[0] + s_rowp[1];
        g_rowsum[2 * blockIdx.x + 1]  = s_rowp[2] + s_rowp[3];
        unsigned long long m0 = s_maxp[0] > s_maxp[1] ? s_maxp[0] : s_maxp[1];
        unsigned long long m1 = s_maxp[2] > s_maxp[3] ? s_maxp[2] : s_maxp[3];
        g_rowstat[2 * blockIdx.x]     = m0;
        g_rowstat[2 * blockIdx.x + 1] = m1;
        unsigned int pc = s_cntp[0] + s_cntp[1] + s_cntp[2] + s_cntp[3];
        if (pc) atomicAdd(&g_pairs, pc);
    }

    // ---- Ticket: last block to finish runs the epilogue.
    __syncthreads();
    __threadfence();
    if (tid == 0) {
        unsigned int t = atomicAdd(&g_done, 1u);
        s_islast = (t == (unsigned)(gridDim.x - 1)) ? 1u : 0u;
    }
    __syncthreads();
    if (!s_islast) return;

    // ---- Phase 2: epilogue on the 256-entry stat arrays.
    const int lane = tid & 31;
    const int wid  = tid >> 5;

    if (tid == 0) {
        g_done = 0u;
        s_cnt[3] = g_pairs;   // pairs
        g_pairs = 0u;
        s_cnt[0] = 0u; s_cnt[1] = 0u; s_cnt[2] = 0u;
    }
    __syncthreads();

    if (tid < LBL) {
        unsigned int rowsum = g_rowsum[tid];
        unsigned long long rmx = g_rowstat[tid];
        unsigned long long c64 = g_col64[tid];
        g_col64[tid] = 0ull;   // re-zero for next replay

        unsigned int psize  = (unsigned int)c64;
        unsigned int colcnt = (unsigned int)(c64 >> 32);
        unsigned int mv     = (unsigned int)(rmx >> 32);
        int          mc     = (int)(rmx & 0xffffffffu);

        s_gt_size[tid]   = rowsum;
        s_pred_size[tid] = psize;
        s_used[tid]      = 0;

        bool has = (tid >= 1) && (2ull * mv > (unsigned long long)rowsum);
        s_best_p[tid] = (short)(has ? mc : 0);
        s_inter[tid]  = has ? mv : 0u;

        unsigned int hb = __ballot_sync(0xffffffffu, has);
        if (lane == 0) s_hasmask[wid] = hb;

        if (tid >= 1) {
            if (colcnt > 1u) atomicAdd(&s_cnt[0], 1u);   // ea
            if (psize  > 0u) atomicAdd(&s_cnt[1], 1u);   // num_pred
            if (rowsum > 0u) atomicAdd(&s_cnt[2], 1u);   // num_gt
        }
    }
    __syncthreads();

    if (tid == 0) {
        unsigned int ea       = s_cnt[0];
        unsigned int num_pred = s_cnt[1];
        unsigned int num_gt   = s_cnt[2];
        unsigned int pairs    = s_cnt[3];

        unsigned int tp = 0;
        float seg_sum = 0.0f;
#pragma unroll
        for (int w = 0; w < LBL / 32; w++) {
            unsigned int m = s_hasmask[w];
            while (m) {
                int bb = __ffs(m) - 1;
                m &= m - 1u;
                int gl = w * 32 + bb;
                int pl = s_best_p[gl];
                if (!s_used[pl]) {
                    unsigned int uni = s_gt_size[gl] + s_pred_size[pl] - s_inter[gl];
                    if (uni < 1u) uni = 1u;
                    seg_sum += (float)s_inter[gl] / (float)uni;
                    s_used[pl] = 1;
                    tp++;
                }
            }
        }
        float ng  = fmaxf((float)num_gt, 1.0f);
        float seg = seg_sum / ng;
        int ns = (int)pairs    - (int)tp;
        int fn = (int)num_gt   - (int)tp;
        int fp = (int)num_pred - (int)tp;
        float det = 1.0f - (float)(fp + fn + ns + (int)ea) / ng;

        bool both_empty = (num_gt == 0u) && (num_pred == 0u);
        bool any_empty  = (num_gt == 0u) || (num_pred == 0u);
        if (both_empty)     { seg = 1.0f; det = 1.0f; }
        else if (any_empty) { seg = 0.0f; det = 0.0f; }

        out[0] = seg;
        out[1] = det;
    }
}

extern "C" void kernel_launch(void* const* d_in, const int* in_sizes, int n_in,
                              void* d_out, int out_size) {
    const int* pred = (const int*)d_in[0];
    const int* gt   = (const int*)d_in[1];
    int n  = in_sizes[0];
    int n4 = n >> 2;

    cudaFuncSetAttribute(hist_kernel,
                         cudaFuncAttributeMaxDynamicSharedMemorySize, 65536);

    hist_kernel<<<GRID, TPB, 65536>>>((const int4*)pred, (const int4*)gt, n4);

    // Tail with PDL: may begin dispatch while hist's flush drains; the
    // device-side cudaGridDependencySynchronize() enforces correctness.
    cudaLaunchConfig_t cfg = {};
    cfg.gridDim = dim3(RGRID, 1, 1);
    cfg.blockDim = dim3(1024, 1, 1);
    cfg.dynamicSmemBytes = 0;
    cfg.stream = 0;
    cudaLaunchAttribute attrs[1];
    attrs[0].id = cudaLaunchAttributeProgrammaticStreamSerialization;
    attrs[0].val.programmaticStreamSerializationAllowed = 1;
    cfg.attrs = attrs;
    cfg.numAttrs = 1;
    cudaLaunchKernelEx(&cfg, tail_kernel, (float*)d_out);
}